// round 5
// baseline (speedup 1.0000x reference)
#include <cuda_runtime.h>
#include <cuda_bf16.h>
#include <cstdint>

#define N_NODES 50000
#define NREL    16
#define NBAS    16
#define DEMB    256
#define DHID    128
#define NEDGE   300000
#define NQUERY  100000
#define CAT     2176   // (1+NREL)*DHID

// ---------------- scratch (static __device__ globals; no allocation) ----------------
__device__ __nv_bfloat16 g_Ehi[(size_t)N_NODES * DEMB];
__device__ __nv_bfloat16 g_Elo[(size_t)N_NODES * DEMB];
__device__ __nv_bfloat16 g_Whi[(size_t)CAT * DEMB];
__device__ __nv_bfloat16 g_Wlo[(size_t)CAT * DEMB];
__device__ __nv_bfloat16 g_xhi[N_NODES * DHID];
__device__ __nv_bfloat16 g_xlo[N_NODES * DHID];
__device__ __nv_bfloat16 g_w1ch[2 * DHID * DHID];   // combined head+tail, transposed
__device__ __nv_bfloat16 g_w1cl[2 * DHID * DHID];
__device__ float g_Z[(size_t)N_NODES * CAT];
__device__ float g_acc[N_NODES * DHID];
__device__ float g_HPTP[(size_t)N_NODES * 2 * DHID];
__device__ float g_rp[NREL * DHID];

__device__ __forceinline__ uint32_t smem_u32(const void* p) {
    uint32_t a;
    asm("{ .reg .u64 t; cvta.to.shared.u64 t, %1; cvt.u32.u64 %0, t; }" : "=r"(a) : "l"(p));
    return a;
}
__device__ __forceinline__ uint32_t pack_bf2(__nv_bfloat16 a, __nv_bfloat16 b) {
    return ((uint32_t)__bfloat16_as_ushort(b) << 16) | __bfloat16_as_ushort(a);
}
__device__ __forceinline__ void ldsm4(uint32_t* r, uint32_t addr) {
    asm volatile("ldmatrix.sync.aligned.m8n8.x4.shared.b16 {%0,%1,%2,%3}, [%4];"
                 : "=r"(r[0]), "=r"(r[1]), "=r"(r[2]), "=r"(r[3]) : "r"(addr));
}
__device__ __forceinline__ void mma_bf16(float* d, const uint32_t* a, uint32_t b0, uint32_t b1) {
    asm volatile(
        "mma.sync.aligned.m16n8k16.row.col.f32.bf16.bf16.f32 "
        "{%0,%1,%2,%3}, {%4,%5,%6,%7}, {%8,%9}, {%0,%1,%2,%3};"
        : "+f"(d[0]), "+f"(d[1]), "+f"(d[2]), "+f"(d[3])
        : "r"(a[0]), "r"(a[1]), "r"(a[2]), "r"(a[3]), "r"(b0), "r"(b1));
}
__device__ __forceinline__ void cp16(uint32_t dst, const void* src, int srcBytes) {
    asm volatile("cp.async.cg.shared.global [%0], [%1], 16, %2;"
                 :: "r"(dst), "l"(src), "r"(srcBytes));
}
#define CP_COMMIT() asm volatile("cp.async.commit_group;" ::: "memory")
template<int Nw> __device__ __forceinline__ void cp_wait() {
    asm volatile("cp.async.wait_group %0;" :: "n"(Nw) : "memory");
}
__device__ __forceinline__ void split1(float v, __nv_bfloat16& h, __nv_bfloat16& l) {
    h = __float2bfloat16(v);
    l = __float2bfloat16(v - __bfloat162float(h));
}

// ============================================================================
// 3xBF16 mma.sync GEMM, cp.async double-buffered, 512 threads (16 warps, 4x4).
// C[M,N] = A[M,K] @ Bt[N,K]^T ; A,B pre-split bf16 hi/lo, row-major stride K.
// grid (N/128, ceil(M/128)), BK=64. Warp tile 32x32.
// ============================================================================
#define TILE_B  16384
#define STAGE_B (4 * TILE_B)          // 64 KB
#define GEMM_SMEM (2 * STAGE_B)       // 128 KB

__global__ __launch_bounds__(512, 1)
void gemm3xb(int M, int K,
             const __nv_bfloat16* __restrict__ Ahi,
             const __nv_bfloat16* __restrict__ Alo,
             const __nv_bfloat16* __restrict__ Bhi,
             const __nv_bfloat16* __restrict__ Blo,
             float* __restrict__ C, int ldc)
{
    extern __shared__ char sm[];
    const uint32_t sbase = smem_u32(sm);

    const int tid  = threadIdx.x;
    const int wid  = tid >> 5;
    const int lane = tid & 31;
    const int wm   = wid & 3;            // 0..3, 32 rows each
    const int wn   = wid >> 2;           // 0..3, 32 cols each
    const int mBase = blockIdx.y * 128;
    const int nBase = blockIdx.x * 128;

    float d[2][4][4];
    #pragma unroll
    for (int i = 0; i < 2; ++i)
        #pragma unroll
        for (int j = 0; j < 4; ++j)
            #pragma unroll
            for (int t = 0; t < 4; ++t) d[i][j][t] = 0.f;

    const int nk = K >> 6;

    // staging: per tile 1024 16B-chunks; 512 threads x 2 iters
    auto issue = [&](int s, int k0) {
        const uint32_t sb = sbase + (uint32_t)s * STAGE_B;
        #pragma unroll
        for (int it = 0; it < 2; ++it) {
            int g = tid + it * 512;
            int row = g >> 3;
            int seg = g & 7;
            uint32_t soff = (uint32_t)(row * 128) + ((uint32_t)(seg ^ (row & 7)) << 4);
            int gr = mBase + row;
            int okA = (gr < M) ? 16 : 0;
            size_t aoff = (size_t)(okA ? gr : 0) * K + k0 + seg * 8;
            cp16(sb + soff,              Ahi + aoff, okA);
            cp16(sb + TILE_B + soff,     Alo + aoff, okA);
            size_t boff = (size_t)(nBase + row) * K + k0 + seg * 8;
            cp16(sb + 2 * TILE_B + soff, Bhi + boff, 16);
            cp16(sb + 3 * TILE_B + soff, Blo + boff, 16);
        }
    };

    const int lrow = lane & 15;
    const int lkh  = lane >> 4;

    issue(0, 0);
    CP_COMMIT();

    for (int c = 0; c < nk; ++c) {
        if (c + 1 < nk) {
            issue((c + 1) & 1, (c + 1) << 6);
            CP_COMMIT();
            cp_wait<1>();
        } else {
            cp_wait<0>();
        }
        __syncthreads();

        const uint32_t bAhi = sbase + (uint32_t)(c & 1) * STAGE_B;
        const uint32_t bAlo = bAhi + TILE_B;
        const uint32_t bBhi = bAhi + 2 * TILE_B;
        const uint32_t bBlo = bAhi + 3 * TILE_B;

        #pragma unroll
        for (int ks = 0; ks < 4; ++ks) {
            uint32_t ah[2][4], al[2][4], bh[2][4], bl[2][4];
            #pragma unroll
            for (int i = 0; i < 2; ++i) {
                int row = wm * 32 + i * 16 + lrow;
                uint32_t seg = (uint32_t)(ks * 2 + lkh) ^ (uint32_t)(row & 7);
                uint32_t off = (uint32_t)(row * 128) + (seg << 4);
                ldsm4(ah[i], bAhi + off);
                ldsm4(al[i], bAlo + off);
            }
            #pragma unroll
            for (int j2 = 0; j2 < 2; ++j2) {
                int row = wn * 32 + j2 * 16 + lrow;
                uint32_t seg = (uint32_t)(ks * 2 + lkh) ^ (uint32_t)(row & 7);
                uint32_t off = (uint32_t)(row * 128) + (seg << 4);
                ldsm4(bh[j2], bBhi + off);
                ldsm4(bl[j2], bBlo + off);
            }
            // pass 0: hh   pass 1: hl   pass 2: lh  — chain distance 8
            #pragma unroll
            for (int p = 0; p < 3; ++p) {
                #pragma unroll
                for (int i = 0; i < 2; ++i) {
                    const uint32_t* aa = (p == 2) ? al[i] : ah[i];
                    #pragma unroll
                    for (int j2 = 0; j2 < 2; ++j2) {
                        const uint32_t* bb = (p == 1) ? bl[j2] : bh[j2];
                        mma_bf16(d[i][j2 * 2],     aa, bb[0], bb[2]);
                        mma_bf16(d[i][j2 * 2 + 1], aa, bb[1], bb[3]);
                    }
                }
            }
        }
        __syncthreads();
    }

    // ---- epilogue ----
    const int q = lane >> 2;
    const int cpair = (lane & 3) * 2;
    #pragma unroll
    for (int i = 0; i < 2; ++i) {
        int gr0 = mBase + wm * 32 + i * 16 + q;
        #pragma unroll
        for (int j = 0; j < 4; ++j) {
            int gc = nBase + wn * 32 + j * 8 + cpair;
            if (gr0 < M)
                *(float2*)(C + (size_t)gr0 * ldc + gc) = make_float2(d[i][j][0], d[i][j][1]);
            if (gr0 + 8 < M)
                *(float2*)(C + (size_t)(gr0 + 8) * ldc + gc) = make_float2(d[i][j][2], d[i][j][3]);
        }
    }
}

// ---------------- split fp32 -> bf16 hi/lo ----------------
__global__ void split_k(const float* __restrict__ x, int n4,
                        __nv_bfloat16* __restrict__ hi, __nv_bfloat16* __restrict__ lo) {
    int i = blockIdx.x * blockDim.x + threadIdx.x;
    if (i >= n4) return;
    float4 v = ((const float4*)x)[i];
    __nv_bfloat16 h0, h1, h2, h3, l0, l1, l2, l3;
    split1(v.x, h0, l0); split1(v.y, h1, l1);
    split1(v.z, h2, l2); split1(v.w, h3, l3);
    ((uint2*)hi)[i] = make_uint2(pack_bf2(h0, h1), pack_bf2(h2, h3));
    ((uint2*)lo)[i] = make_uint2(pack_bf2(l0, l1), pack_bf2(l2, l3));
}

// ---------------- WcatT hi/lo ----------------
__global__ void build_wcatT(const float* __restrict__ bases,
                            const float* __restrict__ coeff,
                            const float* __restrict__ selfw,
                            __nv_bfloat16* __restrict__ Whi,
                            __nv_bfloat16* __restrict__ Wlo, int din) {
    int idx = blockIdx.x * blockDim.x + threadIdx.x;
    if (idx >= CAT * din) return;
    int n = idx / din;
    int k = idx - n * din;
    int blk = n >> 7;
    int j = n & 127;
    float v;
    if (blk == 0) {
        v = selfw[k * DHID + j];
    } else {
        int r = blk - 1;
        v = 0.f;
        #pragma unroll
        for (int b = 0; b < NBAS; ++b)
            v += coeff[r * NBAS + b] * bases[((size_t)b * din + k) * DHID + j];
    }
    __nv_bfloat16 h, l;
    split1(v, h, l);
    Whi[idx] = h;
    Wlo[idx] = l;
}

// ---------------- combined transposed w1 head+tail blocks, hi/lo ----------------
__global__ void transpose_w1(const float* __restrict__ w1,
                             __nv_bfloat16* __restrict__ ch, __nv_bfloat16* __restrict__ cl) {
    int idx = blockIdx.x * blockDim.x + threadIdx.x;
    if (idx >= 2 * DHID * DHID) return;
    int n = idx >> 7;           // 0..255
    int k = idx & 127;
    float v = (n < DHID) ? w1[(size_t)k * DHID + n]
                         : w1[(size_t)(384 + k) * DHID + (n - DHID)];
    __nv_bfloat16 h, l;
    split1(v, h, l);
    ch[idx] = h; cl[idx] = l;
}

// ---------------- init accumulator from self-loop block of Z ----------------
__global__ void init_self(const float* __restrict__ Z, float* __restrict__ acc) {
    int idx = blockIdx.x * blockDim.x + threadIdx.x;
    if (idx >= N_NODES * DHID) return;
    int n = idx >> 7;
    int j = idx & 127;
    acc[idx] = Z[(size_t)n * CAT + j];
}

// ---------------- edge scatter ----------------
__global__ void edge_scatter(const int* __restrict__ erow,
                             const int* __restrict__ ecol,
                             const int* __restrict__ etype,
                             const float* __restrict__ Z,
                             float* __restrict__ acc) {
    int e = blockIdx.x * 8 + (threadIdx.x >> 5);
    if (e >= NEDGE) return;
    int lane = threadIdx.x & 31;
    int r = erow[e], c = ecol[e], t = etype[e];
    float4 v = ((const float4*)(Z + (size_t)c * CAT + (size_t)(1 + t) * DHID))[lane];
    float* dst = acc + (size_t)r * DHID + lane * 4;
    atomicAdd(dst + 0, v.x);
    atomicAdd(dst + 1, v.y);
    atomicAdd(dst + 2, v.z);
    atomicAdd(dst + 3, v.w);
}

// ---------------- relu + layernorm -> bf16 hi/lo ----------------
__global__ void relu_ln(const float* __restrict__ acc,
                        const float* __restrict__ gamma,
                        const float* __restrict__ beta,
                        __nv_bfloat16* __restrict__ xhi,
                        __nv_bfloat16* __restrict__ xlo) {
    int n = blockIdx.x * 8 + (threadIdx.x >> 5);
    if (n >= N_NODES) return;
    int lane = threadIdx.x & 31;
    float4 v = ((const float4*)(acc + (size_t)n * DHID))[lane];
    v.x = fmaxf(v.x, 0.f); v.y = fmaxf(v.y, 0.f);
    v.z = fmaxf(v.z, 0.f); v.w = fmaxf(v.w, 0.f);
    float s = v.x + v.y + v.z + v.w;
    #pragma unroll
    for (int o = 16; o; o >>= 1) s += __shfl_xor_sync(0xFFFFFFFFu, s, o);
    float mu = s * (1.f / DHID);
    float dx = v.x - mu, dy = v.y - mu, dz = v.z - mu, dw = v.w - mu;
    float ss = dx * dx + dy * dy + dz * dz + dw * dw;
    #pragma unroll
    for (int o = 16; o; o >>= 1) ss += __shfl_xor_sync(0xFFFFFFFFu, ss, o);
    float inv = rsqrtf(ss * (1.f / DHID) + 1e-5f);
    float4 g = ((const float4*)gamma)[lane];
    float4 b = ((const float4*)beta)[lane];
    float ox = dx * inv * g.x + b.x;
    float oy = dy * inv * g.y + b.y;
    float oz = dz * inv * g.z + b.z;
    float ow = dw * inv * g.w + b.w;
    __nv_bfloat16 h0, h1, h2, h3, l0, l1, l2, l3;
    split1(ox, h0, l0); split1(oy, h1, l1);
    split1(oz, h2, l2); split1(ow, h3, l3);
    ((uint2*)(xhi + (size_t)n * DHID))[lane] = make_uint2(pack_bf2(h0, h1), pack_bf2(h2, h3));
    ((uint2*)(xlo + (size_t)n * DHID))[lane] = make_uint2(pack_bf2(l0, l1), pack_bf2(l2, l3));
}

// ---------------- relproj ----------------
__global__ void relproj_k(const float* __restrict__ relemb,
                          const float* __restrict__ w1,
                          const float* __restrict__ b1,
                          float* __restrict__ rp) {
    int idx = blockIdx.x * blockDim.x + threadIdx.x;
    if (idx >= NREL * DHID) return;
    int r = idx >> 7;
    int j = idx & 127;
    float s = b1[j];
    for (int i = 0; i < DEMB; ++i)
        s = fmaf(relemb[r * DEMB + i], w1[(DHID + i) * DHID + j], s);
    rp[idx] = s;
}

// ---------------- score (HPTP combined, ld=256) ----------------
__global__ void score_k(const int* __restrict__ head,
                        const int* __restrict__ rel,
                        const int* __restrict__ tail,
                        const float* __restrict__ HPTP,
                        const float* __restrict__ rp,
                        const float* __restrict__ w2,
                        const float* __restrict__ b2,
                        float* __restrict__ out) {
    int q = blockIdx.x * 8 + (threadIdx.x >> 5);
    if (q >= NQUERY) return;
    int lane = threadIdx.x & 31;
    int h = head[q], r = rel[q], t = tail[q];
    float4 a = ((const float4*)(HPTP + (size_t)h * 256))[lane];
    float4 bb = ((const float4*)(HPTP + (size_t)t * 256 + DHID))[lane];
    float4 c = ((const float4*)(rp + (size_t)r * DHID))[lane];
    float4 w = ((const float4*)w2)[lane];
    float s = fmaxf(a.x + bb.x + c.x, 0.f) * w.x
            + fmaxf(a.y + bb.y + c.y, 0.f) * w.y
            + fmaxf(a.z + bb.z + c.z, 0.f) * w.z
            + fmaxf(a.w + bb.w + c.w, 0.f) * w.w;
    #pragma unroll
    for (int o = 16; o; o >>= 1) s += __shfl_xor_sync(0xFFFFFFFFu, s, o);
    if (lane == 0) out[q] = s + b2[0];
}

// ---------------- launch ----------------
extern "C" void kernel_launch(void* const* d_in, const int* in_sizes, int n_in,
                              void* d_out, int out_size) {
    (void)in_sizes; (void)n_in; (void)out_size;
    const int*   edge_index   = (const int*)d_in[0];
    const int*   edge_type    = (const int*)d_in[1];
    const int*   head_ids     = (const int*)d_in[2];
    const int*   relation_ids = (const int*)d_in[3];
    const int*   tail_ids     = (const int*)d_in[4];
    const float* entity_emb   = (const float*)d_in[5];
    const float* relation_emb = (const float*)d_in[6];
    const float* bases0       = (const float*)d_in[7];
    const float* coeff0       = (const float*)d_in[8];
    const float* selfw0       = (const float*)d_in[9];
    const float* bases1       = (const float*)d_in[10];
    const float* coeff1       = (const float*)d_in[11];
    const float* selfw1       = (const float*)d_in[12];
    const float* ln0_g        = (const float*)d_in[13];
    const float* ln0_b        = (const float*)d_in[14];
    const float* ln1_g        = (const float*)d_in[15];
    const float* ln1_b        = (const float*)d_in[16];
    const float* w1           = (const float*)d_in[17];
    const float* b1           = (const float*)d_in[18];
    const float* w2           = (const float*)d_in[19];
    const float* b2           = (const float*)d_in[20];
    float* out = (float*)d_out;

    __nv_bfloat16 *Ehi, *Elo, *Whi, *Wlo, *xhi, *xlo, *w1ch, *w1cl;
    float *Z, *acc, *HPTP, *rp;
    cudaGetSymbolAddress((void**)&Ehi, g_Ehi);
    cudaGetSymbolAddress((void**)&Elo, g_Elo);
    cudaGetSymbolAddress((void**)&Whi, g_Whi);
    cudaGetSymbolAddress((void**)&Wlo, g_Wlo);
    cudaGetSymbolAddress((void**)&xhi, g_xhi);
    cudaGetSymbolAddress((void**)&xlo, g_xlo);
    cudaGetSymbolAddress((void**)&w1ch, g_w1ch);
    cudaGetSymbolAddress((void**)&w1cl, g_w1cl);
    cudaGetSymbolAddress((void**)&Z,    g_Z);
    cudaGetSymbolAddress((void**)&acc,  g_acc);
    cudaGetSymbolAddress((void**)&HPTP, g_HPTP);
    cudaGetSymbolAddress((void**)&rp,   g_rp);

    cudaFuncSetAttribute(gemm3xb, cudaFuncAttributeMaxDynamicSharedMemorySize, GEMM_SMEM);

    const int* erow = edge_index;
    const int* ecol = edge_index + NEDGE;

    dim3 gz(CAT / 128, (N_NODES + 127) / 128);   // 17 x 391
    dim3 gh(2, (N_NODES + 127) / 128);           // combined head+tail

    // ----- layer 0 -----
    split_k<<<(N_NODES * DEMB / 4 + 255) / 256, 256>>>(entity_emb, N_NODES * DEMB / 4, Ehi, Elo);
    build_wcatT<<<(CAT * DEMB + 255) / 256, 256>>>(bases0, coeff0, selfw0, Whi, Wlo, DEMB);
    gemm3xb<<<gz, 512, GEMM_SMEM>>>(N_NODES, DEMB, Ehi, Elo, Whi, Wlo, Z, CAT);
    init_self<<<(N_NODES * DHID + 255) / 256, 256>>>(Z, acc);
    edge_scatter<<<(NEDGE + 7) / 8, 256>>>(erow, ecol, edge_type, Z, acc);
    relu_ln<<<(N_NODES + 7) / 8, 256>>>(acc, ln0_g, ln0_b, xhi, xlo);

    // ----- layer 1 -----
    build_wcatT<<<(CAT * DHID + 255) / 256, 256>>>(bases1, coeff1, selfw1, Whi, Wlo, DHID);
    gemm3xb<<<gz, 512, GEMM_SMEM>>>(N_NODES, DHID, xhi, xlo, Whi, Wlo, Z, CAT);
    init_self<<<(N_NODES * DHID + 255) / 256, 256>>>(Z, acc);
    edge_scatter<<<(NEDGE + 7) / 8, 256>>>(erow, ecol, edge_type, Z, acc);
    relu_ln<<<(N_NODES + 7) / 8, 256>>>(acc, ln1_g, ln1_b, xhi, xlo);

    // ----- scoring -----
    relproj_k<<<(NREL * DHID + 255) / 256, 256>>>(relation_emb, w1, b1, rp);
    transpose_w1<<<(2 * DHID * DHID + 255) / 256, 256>>>(w1, w1ch, w1cl);
    gemm3xb<<<gh, 512, GEMM_SMEM>>>(N_NODES, DHID, xhi, xlo, w1ch, w1cl, HPTP, 256);
    score_k<<<(NQUERY + 7) / 8, 256>>>(head_ids, relation_ids, tail_ids, HPTP, rp, w2, b2, out);
}

// round 6
// speedup vs baseline: 2.0507x; 2.0507x over previous
#include <cuda_runtime.h>
#include <cuda_bf16.h>
#include <cstdint>

#define N_NODES 50000
#define NREL    16
#define NBAS    16
#define DEMB    256
#define DHID    128
#define NEDGE   300000
#define NQUERY  100000
#define EGRID   ((NEDGE + 127) / 128 + 16)   // upper bound on total edge tiles

// ---------------- scratch (static __device__ globals; no allocation) ----------------
__device__ __nv_bfloat16 g_Ehi[(size_t)N_NODES * DEMB];
__device__ __nv_bfloat16 g_Elo[(size_t)N_NODES * DEMB];
__device__ __nv_bfloat16 g_Whi[(size_t)NREL * DHID * DEMB];   // relation weights, transposed
__device__ __nv_bfloat16 g_Wlo[(size_t)NREL * DHID * DEMB];
__device__ __nv_bfloat16 g_Shi[DHID * DEMB];                  // selfw transposed
__device__ __nv_bfloat16 g_Slo[DHID * DEMB];
__device__ __nv_bfloat16 g_xhi[N_NODES * DHID];
__device__ __nv_bfloat16 g_xlo[N_NODES * DHID];
__device__ __nv_bfloat16 g_w1ch[2 * DHID * DHID];
__device__ __nv_bfloat16 g_w1cl[2 * DHID * DHID];
__device__ float g_acc[N_NODES * DHID];
__device__ float g_HPTP[(size_t)N_NODES * 2 * DHID];
__device__ float g_rp[NREL * DHID];
// edge sort
__device__ int g_cnt[NREL];
__device__ int g_off[NREL + 1];
__device__ int g_tilestart[NREL + 1];
__device__ int g_cursor[NREL];
__device__ int g_erow_s[NEDGE];
__device__ int g_ecol_s[NEDGE];

__device__ __forceinline__ uint32_t smem_u32(const void* p) {
    uint32_t a;
    asm("{ .reg .u64 t; cvta.to.shared.u64 t, %1; cvt.u32.u64 %0, t; }" : "=r"(a) : "l"(p));
    return a;
}
__device__ __forceinline__ uint32_t pack_bf2(__nv_bfloat16 a, __nv_bfloat16 b) {
    return ((uint32_t)__bfloat16_as_ushort(b) << 16) | __bfloat16_as_ushort(a);
}
__device__ __forceinline__ void ldsm4(uint32_t* r, uint32_t addr) {
    asm volatile("ldmatrix.sync.aligned.m8n8.x4.shared.b16 {%0,%1,%2,%3}, [%4];"
                 : "=r"(r[0]), "=r"(r[1]), "=r"(r[2]), "=r"(r[3]) : "r"(addr));
}
__device__ __forceinline__ void mma_bf16(float* d, const uint32_t* a, uint32_t b0, uint32_t b1) {
    asm volatile(
        "mma.sync.aligned.m16n8k16.row.col.f32.bf16.bf16.f32 "
        "{%0,%1,%2,%3}, {%4,%5,%6,%7}, {%8,%9}, {%0,%1,%2,%3};"
        : "+f"(d[0]), "+f"(d[1]), "+f"(d[2]), "+f"(d[3])
        : "r"(a[0]), "r"(a[1]), "r"(a[2]), "r"(a[3]), "r"(b0), "r"(b1));
}
__device__ __forceinline__ void cp16(uint32_t dst, const void* src, int srcBytes) {
    asm volatile("cp.async.cg.shared.global [%0], [%1], 16, %2;"
                 :: "r"(dst), "l"(src), "r"(srcBytes));
}
#define CP_COMMIT() asm volatile("cp.async.commit_group;" ::: "memory")
template<int Nw> __device__ __forceinline__ void cp_wait() {
    asm volatile("cp.async.wait_group %0;" :: "n"(Nw) : "memory");
}
__device__ __forceinline__ void split1(float v, __nv_bfloat16& h, __nv_bfloat16& l) {
    h = __float2bfloat16(v);
    l = __float2bfloat16(v - __bfloat162float(h));
}
__device__ __forceinline__ void red_add(float* p, float v) {
    asm volatile("red.global.add.f32 [%0], %1;" :: "l"(p), "f"(v) : "memory");
}

#define TILE_B  16384
#define STAGE_B (4 * TILE_B)          // 64 KB
#define GEMM_SMEM (2 * STAGE_B)       // 128 KB

// ============================================================================
// Dense 3xBF16 GEMM (self-loop + HPTP): C[M,N] = A[M,K] @ Bt[N,K]^T
// grid (N/128, ceil(M/128)), 512 threads, warps 4x4, warp tile 32x32
// ============================================================================
__global__ __launch_bounds__(512, 1)
void gemm3xb(int M, int K,
             const __nv_bfloat16* __restrict__ Ahi,
             const __nv_bfloat16* __restrict__ Alo,
             const __nv_bfloat16* __restrict__ Bhi,
             const __nv_bfloat16* __restrict__ Blo,
             float* __restrict__ C, int ldc)
{
    extern __shared__ char sm[];
    const uint32_t sbase = smem_u32(sm);
    const int tid  = threadIdx.x;
    const int wid  = tid >> 5;
    const int lane = tid & 31;
    const int wm   = wid & 3;
    const int wn   = wid >> 2;
    const int mBase = blockIdx.y * 128;
    const int nBase = blockIdx.x * 128;

    float d[2][4][4];
    #pragma unroll
    for (int i = 0; i < 2; ++i)
        #pragma unroll
        for (int j = 0; j < 4; ++j)
            #pragma unroll
            for (int t = 0; t < 4; ++t) d[i][j][t] = 0.f;

    const int nk = K >> 6;

    auto issue = [&](int s, int k0) {
        const uint32_t sb = sbase + (uint32_t)s * STAGE_B;
        #pragma unroll
        for (int it = 0; it < 2; ++it) {
            int g = tid + it * 512;
            int row = g >> 3;
            int seg = g & 7;
            uint32_t soff = (uint32_t)(row * 128) + ((uint32_t)(seg ^ (row & 7)) << 4);
            int gr = mBase + row;
            int okA = (gr < M) ? 16 : 0;
            size_t aoff = (size_t)(okA ? gr : 0) * K + k0 + seg * 8;
            cp16(sb + soff,              Ahi + aoff, okA);
            cp16(sb + TILE_B + soff,     Alo + aoff, okA);
            size_t boff = (size_t)(nBase + row) * K + k0 + seg * 8;
            cp16(sb + 2 * TILE_B + soff, Bhi + boff, 16);
            cp16(sb + 3 * TILE_B + soff, Blo + boff, 16);
        }
    };

    const int lrow = lane & 15;
    const int lkh  = lane >> 4;

    issue(0, 0);
    CP_COMMIT();

    for (int c = 0; c < nk; ++c) {
        if (c + 1 < nk) {
            issue((c + 1) & 1, (c + 1) << 6);
            CP_COMMIT();
            cp_wait<1>();
        } else {
            cp_wait<0>();
        }
        __syncthreads();

        const uint32_t bAhi = sbase + (uint32_t)(c & 1) * STAGE_B;
        const uint32_t bAlo = bAhi + TILE_B;
        const uint32_t bBhi = bAhi + 2 * TILE_B;
        const uint32_t bBlo = bAhi + 3 * TILE_B;

        #pragma unroll
        for (int ks = 0; ks < 4; ++ks) {
            uint32_t ah[2][4], al[2][4], bh[2][4], bl[2][4];
            #pragma unroll
            for (int i = 0; i < 2; ++i) {
                int row = wm * 32 + i * 16 + lrow;
                uint32_t seg = (uint32_t)(ks * 2 + lkh) ^ (uint32_t)(row & 7);
                uint32_t off = (uint32_t)(row * 128) + (seg << 4);
                ldsm4(ah[i], bAhi + off);
                ldsm4(al[i], bAlo + off);
            }
            #pragma unroll
            for (int j2 = 0; j2 < 2; ++j2) {
                int row = wn * 32 + j2 * 16 + lrow;
                uint32_t seg = (uint32_t)(ks * 2 + lkh) ^ (uint32_t)(row & 7);
                uint32_t off = (uint32_t)(row * 128) + (seg << 4);
                ldsm4(bh[j2], bBhi + off);
                ldsm4(bl[j2], bBlo + off);
            }
            #pragma unroll
            for (int p = 0; p < 3; ++p) {
                #pragma unroll
                for (int i = 0; i < 2; ++i) {
                    const uint32_t* aa = (p == 2) ? al[i] : ah[i];
                    #pragma unroll
                    for (int j2 = 0; j2 < 2; ++j2) {
                        const uint32_t* bb = (p == 1) ? bl[j2] : bh[j2];
                        mma_bf16(d[i][j2 * 2],     aa, bb[0], bb[2]);
                        mma_bf16(d[i][j2 * 2 + 1], aa, bb[1], bb[3]);
                    }
                }
            }
        }
        __syncthreads();
    }

    const int q = lane >> 2;
    const int cpair = (lane & 3) * 2;
    #pragma unroll
    for (int i = 0; i < 2; ++i) {
        int gr0 = mBase + wm * 32 + i * 16 + q;
        #pragma unroll
        for (int j = 0; j < 4; ++j) {
            int gc = nBase + wn * 32 + j * 8 + cpair;
            if (gr0 < M)
                *(float2*)(C + (size_t)gr0 * ldc + gc) = make_float2(d[i][j][0], d[i][j][1]);
            if (gr0 + 8 < M)
                *(float2*)(C + (size_t)(gr0 + 8) * ldc + gc) = make_float2(d[i][j][2], d[i][j][3]);
        }
    }
}

// ============================================================================
// Edge GEMM: for each 128-edge tile of relation r:
//   acc[row[e], :] += x[col[e], :] @ W_r^T      (atomic epilogue)
// grid: EGRID blocks x 512 threads. Tile -> relation via g_tilestart.
// ============================================================================
__global__ __launch_bounds__(512, 1)
void egemm(int K,
           const __nv_bfloat16* __restrict__ Ahi,
           const __nv_bfloat16* __restrict__ Alo,
           const __nv_bfloat16* __restrict__ Whi,
           const __nv_bfloat16* __restrict__ Wlo,
           float* __restrict__ acc)
{
    extern __shared__ char sm[];
    __shared__ int s_ecol[128];
    __shared__ int s_erow[128];
    const uint32_t sbase = smem_u32(sm);

    const int bid = blockIdx.x;
    if (bid >= g_tilestart[NREL]) return;
    int r = 0;
    #pragma unroll
    for (int i = 0; i < NREL - 1; ++i)
        if (bid >= g_tilestart[i + 1]) r = i + 1;
    const int tile = bid - g_tilestart[r];
    const int estart = g_off[r] + tile * 128;
    const int medge = min(128, g_off[r + 1] - estart);

    const int tid  = threadIdx.x;
    const int wid  = tid >> 5;
    const int lane = tid & 31;
    const int wm   = wid & 3;
    const int wn   = wid >> 2;

    if (tid < 128) {
        bool ok = tid < medge;
        s_ecol[tid] = ok ? g_ecol_s[estart + tid] : 0;
        s_erow[tid] = ok ? g_erow_s[estart + tid] : -1;
    }
    __syncthreads();

    const __nv_bfloat16* Bhi = Whi + (size_t)r * DHID * K;
    const __nv_bfloat16* Blo = Wlo + (size_t)r * DHID * K;

    float d[2][4][4];
    #pragma unroll
    for (int i = 0; i < 2; ++i)
        #pragma unroll
        for (int j = 0; j < 4; ++j)
            #pragma unroll
            for (int t = 0; t < 4; ++t) d[i][j][t] = 0.f;

    const int nk = K >> 6;

    auto issue = [&](int s, int k0) {
        const uint32_t sb = sbase + (uint32_t)s * STAGE_B;
        #pragma unroll
        for (int it = 0; it < 2; ++it) {
            int g = tid + it * 512;
            int row = g >> 3;
            int seg = g & 7;
            uint32_t soff = (uint32_t)(row * 128) + ((uint32_t)(seg ^ (row & 7)) << 4);
            size_t aoff = (size_t)s_ecol[row] * K + k0 + seg * 8;
            cp16(sb + soff,              Ahi + aoff, 16);
            cp16(sb + TILE_B + soff,     Alo + aoff, 16);
            size_t boff = (size_t)row * K + k0 + seg * 8;
            cp16(sb + 2 * TILE_B + soff, Bhi + boff, 16);
            cp16(sb + 3 * TILE_B + soff, Blo + boff, 16);
        }
    };

    const int lrow = lane & 15;
    const int lkh  = lane >> 4;

    issue(0, 0);
    CP_COMMIT();

    for (int c = 0; c < nk; ++c) {
        if (c + 1 < nk) {
            issue((c + 1) & 1, (c + 1) << 6);
            CP_COMMIT();
            cp_wait<1>();
        } else {
            cp_wait<0>();
        }
        __syncthreads();

        const uint32_t bAhi = sbase + (uint32_t)(c & 1) * STAGE_B;
        const uint32_t bAlo = bAhi + TILE_B;
        const uint32_t bBhi = bAhi + 2 * TILE_B;
        const uint32_t bBlo = bAhi + 3 * TILE_B;

        #pragma unroll
        for (int ks = 0; ks < 4; ++ks) {
            uint32_t ah[2][4], al[2][4], bh[2][4], bl[2][4];
            #pragma unroll
            for (int i = 0; i < 2; ++i) {
                int row = wm * 32 + i * 16 + lrow;
                uint32_t seg = (uint32_t)(ks * 2 + lkh) ^ (uint32_t)(row & 7);
                uint32_t off = (uint32_t)(row * 128) + (seg << 4);
                ldsm4(ah[i], bAhi + off);
                ldsm4(al[i], bAlo + off);
            }
            #pragma unroll
            for (int j2 = 0; j2 < 2; ++j2) {
                int row = wn * 32 + j2 * 16 + lrow;
                uint32_t seg = (uint32_t)(ks * 2 + lkh) ^ (uint32_t)(row & 7);
                uint32_t off = (uint32_t)(row * 128) + (seg << 4);
                ldsm4(bh[j2], bBhi + off);
                ldsm4(bl[j2], bBlo + off);
            }
            #pragma unroll
            for (int p = 0; p < 3; ++p) {
                #pragma unroll
                for (int i = 0; i < 2; ++i) {
                    const uint32_t* aa = (p == 2) ? al[i] : ah[i];
                    #pragma unroll
                    for (int j2 = 0; j2 < 2; ++j2) {
                        const uint32_t* bb = (p == 1) ? bl[j2] : bh[j2];
                        mma_bf16(d[i][j2 * 2],     aa, bb[0], bb[2]);
                        mma_bf16(d[i][j2 * 2 + 1], aa, bb[1], bb[3]);
                    }
                }
            }
        }
        __syncthreads();
    }

    // ---- epilogue: atomic scatter-add to acc ----
    const int q = lane >> 2;
    const int cpair = (lane & 3) * 2;
    #pragma unroll
    for (int i = 0; i < 2; ++i) {
        int le0 = wm * 32 + i * 16 + q;
        int gr0 = s_erow[le0];
        int gr1 = s_erow[le0 + 8];
        #pragma unroll
        for (int j = 0; j < 4; ++j) {
            int gc = wn * 32 + j * 8 + cpair;
            if (gr0 >= 0) {
                float* p = acc + (size_t)gr0 * DHID + gc;
                red_add(p,     d[i][j][0]);
                red_add(p + 1, d[i][j][1]);
            }
            if (gr1 >= 0) {
                float* p = acc + (size_t)gr1 * DHID + gc;
                red_add(p,     d[i][j][2]);
                red_add(p + 1, d[i][j][3]);
            }
        }
    }
}

// ---------------- edge sort (counting sort by relation) ----------------
__global__ void zero16() {
    if (threadIdx.x < NREL) g_cnt[threadIdx.x] = 0;
}
__global__ void hist_k(const int* __restrict__ et) {
    __shared__ int h[NREL];
    if (threadIdx.x < NREL) h[threadIdx.x] = 0;
    __syncthreads();
    int i = blockIdx.x * 256 + threadIdx.x;
    if (i < NEDGE) atomicAdd(&h[et[i]], 1);
    __syncthreads();
    if (threadIdx.x < NREL && h[threadIdx.x]) atomicAdd(&g_cnt[threadIdx.x], h[threadIdx.x]);
}
__global__ void prefix_k() {
    int o = 0, t = 0;
    for (int r = 0; r < NREL; ++r) {
        g_off[r] = o; g_cursor[r] = o; g_tilestart[r] = t;
        o += g_cnt[r]; t += (g_cnt[r] + 127) >> 7;
    }
    g_off[NREL] = o; g_tilestart[NREL] = t;
}
__global__ void scatter_k(const int* __restrict__ er, const int* __restrict__ ec,
                          const int* __restrict__ et) {
    __shared__ int h[NREL], base[NREL];
    if (threadIdx.x < NREL) h[threadIdx.x] = 0;
    __syncthreads();
    int i = blockIdx.x * 256 + threadIdx.x;
    int t = 0, my = 0;
    bool ok = i < NEDGE;
    if (ok) { t = et[i]; my = atomicAdd(&h[t], 1); }
    __syncthreads();
    if (threadIdx.x < NREL && h[threadIdx.x])
        base[threadIdx.x] = atomicAdd(&g_cursor[threadIdx.x], h[threadIdx.x]);
    __syncthreads();
    if (ok) {
        int p = base[t] + my;
        g_erow_s[p] = er[i];
        g_ecol_s[p] = ec[i];
    }
}

// ---------------- split fp32 -> bf16 hi/lo ----------------
__global__ void split_k(const float* __restrict__ x, int n4,
                        __nv_bfloat16* __restrict__ hi, __nv_bfloat16* __restrict__ lo) {
    int i = blockIdx.x * blockDim.x + threadIdx.x;
    if (i >= n4) return;
    float4 v = ((const float4*)x)[i];
    __nv_bfloat16 h0, h1, h2, h3, l0, l1, l2, l3;
    split1(v.x, h0, l0); split1(v.y, h1, l1);
    split1(v.z, h2, l2); split1(v.w, h3, l3);
    ((uint2*)hi)[i] = make_uint2(pack_bf2(h0, h1), pack_bf2(h2, h3));
    ((uint2*)lo)[i] = make_uint2(pack_bf2(l0, l1), pack_bf2(l2, l3));
}

// ---------------- relation weights W_r^T hi/lo: [r][n=128][k=din] ----------------
__global__ void build_wrT(const float* __restrict__ bases,
                          const float* __restrict__ coeff,
                          __nv_bfloat16* __restrict__ Whi,
                          __nv_bfloat16* __restrict__ Wlo, int din) {
    int idx = blockIdx.x * blockDim.x + threadIdx.x;
    if (idx >= NREL * DHID * din) return;
    int r = idx / (DHID * din);
    int rem = idx - r * DHID * din;
    int n = rem / din;
    int k = rem - n * din;
    float v = 0.f;
    #pragma unroll
    for (int b = 0; b < NBAS; ++b)
        v += coeff[r * NBAS + b] * bases[((size_t)b * din + k) * DHID + n];
    __nv_bfloat16 h, l;
    split1(v, h, l);
    Whi[idx] = h;
    Wlo[idx] = l;
}

// ---------------- selfw^T hi/lo: [n=128][k=din] ----------------
__global__ void build_selfT(const float* __restrict__ selfw,
                            __nv_bfloat16* __restrict__ Shi,
                            __nv_bfloat16* __restrict__ Slo, int din) {
    int idx = blockIdx.x * blockDim.x + threadIdx.x;
    if (idx >= DHID * din) return;
    int n = idx / din;
    int k = idx - n * din;
    __nv_bfloat16 h, l;
    split1(selfw[(size_t)k * DHID + n], h, l);
    Shi[idx] = h;
    Slo[idx] = l;
}

// ---------------- combined transposed w1 head+tail blocks, hi/lo ----------------
__global__ void transpose_w1(const float* __restrict__ w1,
                             __nv_bfloat16* __restrict__ ch, __nv_bfloat16* __restrict__ cl) {
    int idx = blockIdx.x * blockDim.x + threadIdx.x;
    if (idx >= 2 * DHID * DHID) return;
    int n = idx >> 7;
    int k = idx & 127;
    float v = (n < DHID) ? w1[(size_t)k * DHID + n]
                         : w1[(size_t)(384 + k) * DHID + (n - DHID)];
    __nv_bfloat16 h, l;
    split1(v, h, l);
    ch[idx] = h; cl[idx] = l;
}

// ---------------- relu + layernorm -> bf16 hi/lo ----------------
__global__ void relu_ln(const float* __restrict__ acc,
                        const float* __restrict__ gamma,
                        const float* __restrict__ beta,
                        __nv_bfloat16* __restrict__ xhi,
                        __nv_bfloat16* __restrict__ xlo) {
    int n = blockIdx.x * 8 + (threadIdx.x >> 5);
    if (n >= N_NODES) return;
    int lane = threadIdx.x & 31;
    float4 v = ((const float4*)(acc + (size_t)n * DHID))[lane];
    v.x = fmaxf(v.x, 0.f); v.y = fmaxf(v.y, 0.f);
    v.z = fmaxf(v.z, 0.f); v.w = fmaxf(v.w, 0.f);
    float s = v.x + v.y + v.z + v.w;
    #pragma unroll
    for (int o = 16; o; o >>= 1) s += __shfl_xor_sync(0xFFFFFFFFu, s, o);
    float mu = s * (1.f / DHID);
    float dx = v.x - mu, dy = v.y - mu, dz = v.z - mu, dw = v.w - mu;
    float ss = dx * dx + dy * dy + dz * dz + dw * dw;
    #pragma unroll
    for (int o = 16; o; o >>= 1) ss += __shfl_xor_sync(0xFFFFFFFFu, ss, o);
    float inv = rsqrtf(ss * (1.f / DHID) + 1e-5f);
    float4 g = ((const float4*)gamma)[lane];
    float4 b = ((const float4*)beta)[lane];
    float ox = dx * inv * g.x + b.x;
    float oy = dy * inv * g.y + b.y;
    float oz = dz * inv * g.z + b.z;
    float ow = dw * inv * g.w + b.w;
    __nv_bfloat16 h0, h1, h2, h3, l0, l1, l2, l3;
    split1(ox, h0, l0); split1(oy, h1, l1);
    split1(oz, h2, l2); split1(ow, h3, l3);
    ((uint2*)(xhi + (size_t)n * DHID))[lane] = make_uint2(pack_bf2(h0, h1), pack_bf2(h2, h3));
    ((uint2*)(xlo + (size_t)n * DHID))[lane] = make_uint2(pack_bf2(l0, l1), pack_bf2(l2, l3));
}

// ---------------- relproj ----------------
__global__ void relproj_k(const float* __restrict__ relemb,
                          const float* __restrict__ w1,
                          const float* __restrict__ b1,
                          float* __restrict__ rp) {
    int idx = blockIdx.x * blockDim.x + threadIdx.x;
    if (idx >= NREL * DHID) return;
    int r = idx >> 7;
    int j = idx & 127;
    float s = b1[j];
    for (int i = 0; i < DEMB; ++i)
        s = fmaf(relemb[r * DEMB + i], w1[(DHID + i) * DHID + j], s);
    rp[idx] = s;
}

// ---------------- score ----------------
__global__ void score_k(const int* __restrict__ head,
                        const int* __restrict__ rel,
                        const int* __restrict__ tail,
                        const float* __restrict__ HPTP,
                        const float* __restrict__ rp,
                        const float* __restrict__ w2,
                        const float* __restrict__ b2,
                        float* __restrict__ out) {
    int q = blockIdx.x * 8 + (threadIdx.x >> 5);
    if (q >= NQUERY) return;
    int lane = threadIdx.x & 31;
    int h = head[q], r = rel[q], t = tail[q];
    float4 a = ((const float4*)(HPTP + (size_t)h * 256))[lane];
    float4 bb = ((const float4*)(HPTP + (size_t)t * 256 + DHID))[lane];
    float4 c = ((const float4*)(rp + (size_t)r * DHID))[lane];
    float4 w = ((const float4*)w2)[lane];
    float s = fmaxf(a.x + bb.x + c.x, 0.f) * w.x
            + fmaxf(a.y + bb.y + c.y, 0.f) * w.y
            + fmaxf(a.z + bb.z + c.z, 0.f) * w.z
            + fmaxf(a.w + bb.w + c.w, 0.f) * w.w;
    #pragma unroll
    for (int o = 16; o; o >>= 1) s += __shfl_xor_sync(0xFFFFFFFFu, s, o);
    if (lane == 0) out[q] = s + b2[0];
}

// ---------------- launch ----------------
extern "C" void kernel_launch(void* const* d_in, const int* in_sizes, int n_in,
                              void* d_out, int out_size) {
    (void)in_sizes; (void)n_in; (void)out_size;
    const int*   edge_index   = (const int*)d_in[0];
    const int*   edge_type    = (const int*)d_in[1];
    const int*   head_ids     = (const int*)d_in[2];
    const int*   relation_ids = (const int*)d_in[3];
    const int*   tail_ids     = (const int*)d_in[4];
    const float* entity_emb   = (const float*)d_in[5];
    const float* relation_emb = (const float*)d_in[6];
    const float* bases0       = (const float*)d_in[7];
    const float* coeff0       = (const float*)d_in[8];
    const float* selfw0       = (const float*)d_in[9];
    const float* bases1       = (const float*)d_in[10];
    const float* coeff1       = (const float*)d_in[11];
    const float* selfw1       = (const float*)d_in[12];
    const float* ln0_g        = (const float*)d_in[13];
    const float* ln0_b        = (const float*)d_in[14];
    const float* ln1_g        = (const float*)d_in[15];
    const float* ln1_b        = (const float*)d_in[16];
    const float* w1           = (const float*)d_in[17];
    const float* b1           = (const float*)d_in[18];
    const float* w2           = (const float*)d_in[19];
    const float* b2           = (const float*)d_in[20];
    float* out = (float*)d_out;

    __nv_bfloat16 *Ehi, *Elo, *Whi, *Wlo, *Shi, *Slo, *xhi, *xlo, *w1ch, *w1cl;
    float *acc, *HPTP, *rp;
    cudaGetSymbolAddress((void**)&Ehi, g_Ehi);
    cudaGetSymbolAddress((void**)&Elo, g_Elo);
    cudaGetSymbolAddress((void**)&Whi, g_Whi);
    cudaGetSymbolAddress((void**)&Wlo, g_Wlo);
    cudaGetSymbolAddress((void**)&Shi, g_Shi);
    cudaGetSymbolAddress((void**)&Slo, g_Slo);
    cudaGetSymbolAddress((void**)&xhi, g_xhi);
    cudaGetSymbolAddress((void**)&xlo, g_xlo);
    cudaGetSymbolAddress((void**)&w1ch, g_w1ch);
    cudaGetSymbolAddress((void**)&w1cl, g_w1cl);
    cudaGetSymbolAddress((void**)&acc,  g_acc);
    cudaGetSymbolAddress((void**)&HPTP, g_HPTP);
    cudaGetSymbolAddress((void**)&rp,   g_rp);

    cudaFuncSetAttribute(gemm3xb, cudaFuncAttributeMaxDynamicSharedMemorySize, GEMM_SMEM);
    cudaFuncSetAttribute(egemm,   cudaFuncAttributeMaxDynamicSharedMemorySize, GEMM_SMEM);

    const int* erow = edge_index;
    const int* ecol = edge_index + NEDGE;

    const int nM = (N_NODES + 127) / 128;   // 391

    // ----- edge sort by relation -----
    zero16<<<1, 32>>>();
    hist_k<<<(NEDGE + 255) / 256, 256>>>(edge_type);
    prefix_k<<<1, 1>>>();
    scatter_k<<<(NEDGE + 255) / 256, 256>>>(erow, ecol, edge_type);

    // ----- layer 0 -----
    split_k<<<(N_NODES * DEMB / 4 + 255) / 256, 256>>>(entity_emb, N_NODES * DEMB / 4, Ehi, Elo);
    build_wrT<<<(NREL * DHID * DEMB + 255) / 256, 256>>>(bases0, coeff0, Whi, Wlo, DEMB);
    build_selfT<<<(DHID * DEMB + 255) / 256, 256>>>(selfw0, Shi, Slo, DEMB);
    gemm3xb<<<dim3(1, nM), 512, GEMM_SMEM>>>(N_NODES, DEMB, Ehi, Elo, Shi, Slo, acc, DHID);
    egemm<<<EGRID, 512, GEMM_SMEM>>>(DEMB, Ehi, Elo, Whi, Wlo, acc);
    relu_ln<<<(N_NODES + 7) / 8, 256>>>(acc, ln0_g, ln0_b, xhi, xlo);

    // ----- layer 1 -----
    build_wrT<<<(NREL * DHID * DHID + 255) / 256, 256>>>(bases1, coeff1, Whi, Wlo, DHID);
    build_selfT<<<(DHID * DHID + 255) / 256, 256>>>(selfw1, Shi, Slo, DHID);
    gemm3xb<<<dim3(1, nM), 512, GEMM_SMEM>>>(N_NODES, DHID, xhi, xlo, Shi, Slo, acc, DHID);
    egemm<<<EGRID, 512, GEMM_SMEM>>>(DHID, xhi, xlo, Whi, Wlo, acc);
    relu_ln<<<(N_NODES + 7) / 8, 256>>>(acc, ln1_g, ln1_b, xhi, xlo);

    // ----- scoring -----
    relproj_k<<<(NREL * DHID + 255) / 256, 256>>>(relation_emb, w1, b1, rp);
    transpose_w1<<<(2 * DHID * DHID + 255) / 256, 256>>>(w1, w1ch, w1cl);
    gemm3xb<<<dim3(2, nM), 512, GEMM_SMEM>>>(N_NODES, DHID, xhi, xlo, w1ch, w1cl, HPTP, 256);
    score_k<<<(NQUERY + 7) / 8, 256>>>(head_ids, relation_ids, tail_ids, HPTP, rp, w2, b2, out);
}

// round 7
// speedup vs baseline: 2.5571x; 1.2469x over previous
#include <cuda_runtime.h>
#include <cuda_bf16.h>
#include <cstdint>

#define N_NODES 50000
#define NREL    16
#define NBAS    16
#define DEMB    256
#define DHID    128
#define NEDGE   300000
#define NQUERY  100000
#define EGRID   ((NEDGE + 127) / 128 + 16)

// ---------------- scratch (static __device__ globals; no allocation) ----------------
__device__ int8_t g_Eq1[(size_t)N_NODES * DEMB];
__device__ int8_t g_Eq0[(size_t)N_NODES * DEMB];
__device__ float  g_Es[N_NODES];
__device__ int8_t g_Wq1[(size_t)NREL * DHID * DEMB];
__device__ int8_t g_Wq0[(size_t)NREL * DHID * DEMB];
__device__ float  g_Wsc[NREL * DHID];
__device__ int8_t g_Sq1[DHID * DEMB];
__device__ int8_t g_Sq0[DHID * DEMB];
__device__ float  g_Ssc[DHID];
__device__ int8_t g_xq1[N_NODES * DHID];
__device__ int8_t g_xq0[N_NODES * DHID];
__device__ float  g_xs[N_NODES];
__device__ int8_t g_w1q1[2 * DHID * DHID];
__device__ int8_t g_w1q0[2 * DHID * DHID];
__device__ float  g_w1sc[2 * DHID];
__device__ float g_acc[N_NODES * DHID];
__device__ float g_HPTP[(size_t)N_NODES * 2 * DHID];
__device__ float g_rp[NREL * DHID];
// edge sort
__device__ int g_cnt[NREL];
__device__ int g_off[NREL + 1];
__device__ int g_tilestart[NREL + 1];
__device__ int g_cursor[NREL];
__device__ int g_erow_s[NEDGE];
__device__ int g_ecol_s[NEDGE];

__device__ __forceinline__ uint32_t smem_u32(const void* p) {
    uint32_t a;
    asm("{ .reg .u64 t; cvta.to.shared.u64 t, %1; cvt.u32.u64 %0, t; }" : "=r"(a) : "l"(p));
    return a;
}
__device__ __forceinline__ void ldsm4(uint32_t* r, uint32_t addr) {
    asm volatile("ldmatrix.sync.aligned.m8n8.x4.shared.b16 {%0,%1,%2,%3}, [%4];"
                 : "=r"(r[0]), "=r"(r[1]), "=r"(r[2]), "=r"(r[3]) : "r"(addr));
}
__device__ __forceinline__ void mma_s8(int* d, const uint32_t* a, uint32_t b0, uint32_t b1) {
    asm volatile(
        "mma.sync.aligned.m16n8k32.row.col.s32.s8.s8.s32 "
        "{%0,%1,%2,%3}, {%4,%5,%6,%7}, {%8,%9}, {%0,%1,%2,%3};"
        : "+r"(d[0]), "+r"(d[1]), "+r"(d[2]), "+r"(d[3])
        : "r"(a[0]), "r"(a[1]), "r"(a[2]), "r"(a[3]), "r"(b0), "r"(b1));
}
__device__ __forceinline__ void cp16(uint32_t dst, const void* src, int srcBytes) {
    asm volatile("cp.async.cg.shared.global [%0], [%1], 16, %2;"
                 :: "r"(dst), "l"(src), "r"(srcBytes));
}
#define CP_COMMIT() asm volatile("cp.async.commit_group;" ::: "memory")
template<int Nw> __device__ __forceinline__ void cp_wait() {
    asm volatile("cp.async.wait_group %0;" :: "n"(Nw) : "memory");
}
__device__ __forceinline__ void red_add(float* p, float v) {
    asm volatile("red.global.add.f32 [%0], %1;" :: "l"(p), "f"(v) : "memory");
}
__device__ __forceinline__ uint32_t pack4i8(int a, int b, int c, int d) {
    return (uint32_t)(a & 0xff) | ((uint32_t)(b & 0xff) << 8) |
           ((uint32_t)(c & 0xff) << 16) | ((uint32_t)(d & 0xff) << 24);
}
__device__ __forceinline__ void quant1(float v, float inv, int& h, int& l) {
    float q = v * inv;                       // |q| <= 16256
    h = __float2int_rn(q * (1.f / 128.f));
    l = __float2int_rn(q - 128.f * (float)h);
}

#define TILE8  8192                   // 128 rows x 64 bytes
#define STAGE8 (4 * TILE8)            // 32 KB
#define SMEM8  (2 * STAGE8)           // 64 KB

// smem addressing: 64B rows, 4x16B segs, swizzle seg ^= (row>>1)&3
__device__ __forceinline__ uint32_t sw_off(int row, int seg) {
    return (uint32_t)(row * 64) + ((uint32_t)(seg ^ ((row >> 1) & 3)) << 4);
}
// ldmatrix address for int8 16x32B block at base row0, k32 step ks
__device__ __forceinline__ uint32_t lds_addr(uint32_t tb, int row0, int ks, int lane) {
    int row = row0 + (lane & 7) + ((lane >> 3) & 1) * 8;
    int seg = ks * 2 + (lane >> 4);
    return tb + sw_off(row, seg);
}

// ============================================================================
// Dense int8 GEMM: C[M,N] = (Aq,As) @ (Bq,Bs)^T ; grid (N/128, ceil(M/128)), 512 thr
// ============================================================================
__global__ __launch_bounds__(512, 1)
void gemm_s8(int M, int K,
             const int8_t* __restrict__ Aq1, const int8_t* __restrict__ Aq0,
             const float* __restrict__ As,
             const int8_t* __restrict__ Bq1, const int8_t* __restrict__ Bq0,
             const float* __restrict__ Bs,
             float* __restrict__ C, int ldc)
{
    extern __shared__ char sm[];
    const uint32_t sbase = smem_u32(sm);
    const int tid  = threadIdx.x;
    const int wid  = tid >> 5;
    const int lane = tid & 31;
    const int wm   = wid & 3;
    const int wn   = wid >> 2;
    const int mBase = blockIdx.y * 128;
    const int nBase = blockIdx.x * 128;

    int d1[2][4][4], d2[2][4][4];
    #pragma unroll
    for (int i = 0; i < 2; ++i)
        #pragma unroll
        for (int j = 0; j < 4; ++j)
            #pragma unroll
            for (int t = 0; t < 4; ++t) { d1[i][j][t] = 0; d2[i][j][t] = 0; }

    const int nk = K >> 6;

    auto issue = [&](int s, int k0) {
        const uint32_t sb = sbase + (uint32_t)s * STAGE8;
        int row = tid >> 2;
        int seg = tid & 3;
        uint32_t so = sw_off(row, seg);
        int gr = mBase + row;
        int okA = (gr < M) ? 16 : 0;
        size_t aoff = (size_t)(okA ? gr : 0) * K + k0 + seg * 16;
        cp16(sb + so,             Aq1 + aoff, okA);
        cp16(sb + TILE8 + so,     Aq0 + aoff, okA);
        size_t boff = (size_t)(nBase + row) * K + k0 + seg * 16;
        cp16(sb + 2 * TILE8 + so, Bq1 + boff, 16);
        cp16(sb + 3 * TILE8 + so, Bq0 + boff, 16);
    };

    issue(0, 0);
    CP_COMMIT();

    for (int c = 0; c < nk; ++c) {
        if (c + 1 < nk) {
            issue((c + 1) & 1, (c + 1) << 6);
            CP_COMMIT();
            cp_wait<1>();
        } else {
            cp_wait<0>();
        }
        __syncthreads();

        const uint32_t bA1 = sbase + (uint32_t)(c & 1) * STAGE8;
        const uint32_t bA0 = bA1 + TILE8;
        const uint32_t bB1 = bA1 + 2 * TILE8;
        const uint32_t bB0 = bA1 + 3 * TILE8;

        #pragma unroll
        for (int ks = 0; ks < 2; ++ks) {
            uint32_t aq1[2][4], aq0[2][4], bq1[2][4], bq0[2][4];
            #pragma unroll
            for (int i = 0; i < 2; ++i) {
                uint32_t ad = lds_addr(0, wm * 32 + i * 16, ks, lane);
                ldsm4(aq1[i], bA1 + ad);
                ldsm4(aq0[i], bA0 + ad);
            }
            #pragma unroll
            for (int j2 = 0; j2 < 2; ++j2) {
                uint32_t bd = lds_addr(0, wn * 32 + j2 * 16, ks, lane);
                ldsm4(bq1[j2], bB1 + bd);
                ldsm4(bq0[j2], bB0 + bd);
            }
            #pragma unroll
            for (int i = 0; i < 2; ++i)
                #pragma unroll
                for (int j2 = 0; j2 < 2; ++j2) {
                    mma_s8(d1[i][j2 * 2],     aq1[i], bq1[j2][0], bq1[j2][2]);
                    mma_s8(d1[i][j2 * 2 + 1], aq1[i], bq1[j2][1], bq1[j2][3]);
                    mma_s8(d2[i][j2 * 2],     aq1[i], bq0[j2][0], bq0[j2][2]);
                    mma_s8(d2[i][j2 * 2 + 1], aq1[i], bq0[j2][1], bq0[j2][3]);
                    mma_s8(d2[i][j2 * 2],     aq0[i], bq1[j2][0], bq1[j2][2]);
                    mma_s8(d2[i][j2 * 2 + 1], aq0[i], bq1[j2][1], bq1[j2][3]);
                }
        }
        __syncthreads();
    }

    const int q = lane >> 2;
    const int cpair = (lane & 3) * 2;
    #pragma unroll
    for (int i = 0; i < 2; ++i) {
        int gr0 = mBase + wm * 32 + i * 16 + q;
        float sa0 = (gr0 < M) ? As[gr0] : 0.f;
        float sa1 = (gr0 + 8 < M) ? As[gr0 + 8] : 0.f;
        #pragma unroll
        for (int j = 0; j < 4; ++j) {
            int gc = nBase + wn * 32 + j * 8 + cpair;
            float sb0 = Bs[gc], sb1 = Bs[gc + 1];
            if (gr0 < M) {
                float v0 = sa0 * sb0 * fmaf(128.f, (float)d2[i][j][0], 16384.f * (float)d1[i][j][0]);
                float v1 = sa0 * sb1 * fmaf(128.f, (float)d2[i][j][1], 16384.f * (float)d1[i][j][1]);
                *(float2*)(C + (size_t)gr0 * ldc + gc) = make_float2(v0, v1);
            }
            if (gr0 + 8 < M) {
                float v2 = sa1 * sb0 * fmaf(128.f, (float)d2[i][j][2], 16384.f * (float)d1[i][j][2]);
                float v3 = sa1 * sb1 * fmaf(128.f, (float)d2[i][j][3], 16384.f * (float)d1[i][j][3]);
                *(float2*)(C + (size_t)(gr0 + 8) * ldc + gc) = make_float2(v2, v3);
            }
        }
    }
}

// ============================================================================
// Edge int8 GEMM: acc[row[e], :] += x[col[e], :] @ W_r^T  (atomic epilogue)
// ============================================================================
__global__ __launch_bounds__(512, 1)
void egemm_s8(int K,
              const int8_t* __restrict__ Aq1, const int8_t* __restrict__ Aq0,
              const float* __restrict__ As,
              const int8_t* __restrict__ Wq1, const int8_t* __restrict__ Wq0,
              const float* __restrict__ Wsc,
              float* __restrict__ acc)
{
    extern __shared__ char sm[];
    __shared__ int s_ecol[128];
    __shared__ int s_erow[128];
    __shared__ float s_sa[128];
    const uint32_t sbase = smem_u32(sm);

    const int bid = blockIdx.x;
    if (bid >= g_tilestart[NREL]) return;
    int r = 0;
    #pragma unroll
    for (int i = 0; i < NREL - 1; ++i)
        if (bid >= g_tilestart[i + 1]) r = i + 1;
    const int tile = bid - g_tilestart[r];
    const int estart = g_off[r] + tile * 128;
    const int medge = min(128, g_off[r + 1] - estart);

    const int tid  = threadIdx.x;
    const int wid  = tid >> 5;
    const int lane = tid & 31;
    const int wm   = wid & 3;
    const int wn   = wid >> 2;

    if (tid < 128) {
        bool ok = tid < medge;
        int c = ok ? g_ecol_s[estart + tid] : 0;
        s_ecol[tid] = c;
        s_erow[tid] = ok ? g_erow_s[estart + tid] : -1;
        s_sa[tid] = As[c];
    }
    __syncthreads();

    const int8_t* Bq1 = Wq1 + (size_t)r * DHID * K;
    const int8_t* Bq0 = Wq0 + (size_t)r * DHID * K;
    const float*  Bs  = Wsc + r * DHID;

    int d1[2][4][4], d2[2][4][4];
    #pragma unroll
    for (int i = 0; i < 2; ++i)
        #pragma unroll
        for (int j = 0; j < 4; ++j)
            #pragma unroll
            for (int t = 0; t < 4; ++t) { d1[i][j][t] = 0; d2[i][j][t] = 0; }

    const int nk = K >> 6;

    auto issue = [&](int s, int k0) {
        const uint32_t sb = sbase + (uint32_t)s * STAGE8;
        int row = tid >> 2;
        int seg = tid & 3;
        uint32_t so = sw_off(row, seg);
        size_t aoff = (size_t)s_ecol[row] * K + k0 + seg * 16;
        cp16(sb + so,             Aq1 + aoff, 16);
        cp16(sb + TILE8 + so,     Aq0 + aoff, 16);
        size_t boff = (size_t)row * K + k0 + seg * 16;
        cp16(sb + 2 * TILE8 + so, Bq1 + boff, 16);
        cp16(sb + 3 * TILE8 + so, Bq0 + boff, 16);
    };

    issue(0, 0);
    CP_COMMIT();

    for (int c = 0; c < nk; ++c) {
        if (c + 1 < nk) {
            issue((c + 1) & 1, (c + 1) << 6);
            CP_COMMIT();
            cp_wait<1>();
        } else {
            cp_wait<0>();
        }
        __syncthreads();

        const uint32_t bA1 = sbase + (uint32_t)(c & 1) * STAGE8;
        const uint32_t bA0 = bA1 + TILE8;
        const uint32_t bB1 = bA1 + 2 * TILE8;
        const uint32_t bB0 = bA1 + 3 * TILE8;

        #pragma unroll
        for (int ks = 0; ks < 2; ++ks) {
            uint32_t aq1[2][4], aq0[2][4], bq1[2][4], bq0[2][4];
            #pragma unroll
            for (int i = 0; i < 2; ++i) {
                uint32_t ad = lds_addr(0, wm * 32 + i * 16, ks, lane);
                ldsm4(aq1[i], bA1 + ad);
                ldsm4(aq0[i], bA0 + ad);
            }
            #pragma unroll
            for (int j2 = 0; j2 < 2; ++j2) {
                uint32_t bd = lds_addr(0, wn * 32 + j2 * 16, ks, lane);
                ldsm4(bq1[j2], bB1 + bd);
                ldsm4(bq0[j2], bB0 + bd);
            }
            #pragma unroll
            for (int i = 0; i < 2; ++i)
                #pragma unroll
                for (int j2 = 0; j2 < 2; ++j2) {
                    mma_s8(d1[i][j2 * 2],     aq1[i], bq1[j2][0], bq1[j2][2]);
                    mma_s8(d1[i][j2 * 2 + 1], aq1[i], bq1[j2][1], bq1[j2][3]);
                    mma_s8(d2[i][j2 * 2],     aq1[i], bq0[j2][0], bq0[j2][2]);
                    mma_s8(d2[i][j2 * 2 + 1], aq1[i], bq0[j2][1], bq0[j2][3]);
                    mma_s8(d2[i][j2 * 2],     aq0[i], bq1[j2][0], bq1[j2][2]);
                    mma_s8(d2[i][j2 * 2 + 1], aq0[i], bq1[j2][1], bq1[j2][3]);
                }
        }
        __syncthreads();
    }

    const int q = lane >> 2;
    const int cpair = (lane & 3) * 2;
    #pragma unroll
    for (int i = 0; i < 2; ++i) {
        int le0 = wm * 32 + i * 16 + q;
        int gr0 = s_erow[le0];
        int gr1 = s_erow[le0 + 8];
        float sa0 = s_sa[le0];
        float sa1 = s_sa[le0 + 8];
        #pragma unroll
        for (int j = 0; j < 4; ++j) {
            int gc = wn * 32 + j * 8 + cpair;
            float sb0 = Bs[gc], sb1 = Bs[gc + 1];
            if (gr0 >= 0) {
                float* p = acc + (size_t)gr0 * DHID + gc;
                red_add(p,     sa0 * sb0 * fmaf(128.f, (float)d2[i][j][0], 16384.f * (float)d1[i][j][0]));
                red_add(p + 1, sa0 * sb1 * fmaf(128.f, (float)d2[i][j][1], 16384.f * (float)d1[i][j][1]));
            }
            if (gr1 >= 0) {
                float* p = acc + (size_t)gr1 * DHID + gc;
                red_add(p,     sa1 * sb0 * fmaf(128.f, (float)d2[i][j][2], 16384.f * (float)d1[i][j][2]));
                red_add(p + 1, sa1 * sb1 * fmaf(128.f, (float)d2[i][j][3], 16384.f * (float)d1[i][j][3]));
            }
        }
    }
}

// ---------------- edge sort (counting sort by relation) ----------------
__global__ void zero16() {
    if (threadIdx.x < NREL) g_cnt[threadIdx.x] = 0;
}
__global__ void hist_k(const int* __restrict__ et) {
    __shared__ int h[NREL];
    if (threadIdx.x < NREL) h[threadIdx.x] = 0;
    __syncthreads();
    int i = blockIdx.x * 256 + threadIdx.x;
    if (i < NEDGE) atomicAdd(&h[et[i]], 1);
    __syncthreads();
    if (threadIdx.x < NREL && h[threadIdx.x]) atomicAdd(&g_cnt[threadIdx.x], h[threadIdx.x]);
}
__global__ void prefix_k() {
    int o = 0, t = 0;
    for (int r = 0; r < NREL; ++r) {
        g_off[r] = o; g_cursor[r] = o; g_tilestart[r] = t;
        o += g_cnt[r]; t += (g_cnt[r] + 127) >> 7;
    }
    g_off[NREL] = o; g_tilestart[NREL] = t;
}
__global__ void scatter_k(const int* __restrict__ er, const int* __restrict__ ec,
                          const int* __restrict__ et) {
    __shared__ int h[NREL], base[NREL];
    if (threadIdx.x < NREL) h[threadIdx.x] = 0;
    __syncthreads();
    int i = blockIdx.x * 256 + threadIdx.x;
    int t = 0, my = 0;
    bool ok = i < NEDGE;
    if (ok) { t = et[i]; my = atomicAdd(&h[t], 1); }
    __syncthreads();
    if (threadIdx.x < NREL && h[threadIdx.x])
        base[threadIdx.x] = atomicAdd(&g_cursor[threadIdx.x], h[threadIdx.x]);
    __syncthreads();
    if (ok) {
        int p = base[t] + my;
        g_erow_s[p] = er[i];
        g_ecol_s[p] = ec[i];
    }
}

// ---------------- quantize entity embeddings (K=256, warp per row) ----------------
__global__ void quantE(const float* __restrict__ E,
                       int8_t* __restrict__ q1, int8_t* __restrict__ q0,
                       float* __restrict__ s) {
    int row = blockIdx.x * 8 + (threadIdx.x >> 5);
    if (row >= N_NODES) return;
    int lane = threadIdx.x & 31;
    const float* rp_ = E + (size_t)row * DEMB;
    float4 v0 = ((const float4*)rp_)[lane * 2];
    float4 v1 = ((const float4*)rp_)[lane * 2 + 1];
    float mx = fmaxf(fmaxf(fmaxf(fabsf(v0.x), fabsf(v0.y)), fmaxf(fabsf(v0.z), fabsf(v0.w))),
                     fmaxf(fmaxf(fabsf(v1.x), fabsf(v1.y)), fmaxf(fabsf(v1.z), fabsf(v1.w))));
    #pragma unroll
    for (int o = 16; o; o >>= 1) mx = fmaxf(mx, __shfl_xor_sync(0xFFFFFFFFu, mx, o));
    mx = fmaxf(mx, 1e-35f);
    float inv = 16256.f / mx;
    int h[8], l[8];
    quant1(v0.x, inv, h[0], l[0]); quant1(v0.y, inv, h[1], l[1]);
    quant1(v0.z, inv, h[2], l[2]); quant1(v0.w, inv, h[3], l[3]);
    quant1(v1.x, inv, h[4], l[4]); quant1(v1.y, inv, h[5], l[5]);
    quant1(v1.z, inv, h[6], l[6]); quant1(v1.w, inv, h[7], l[7]);
    uint32_t* p1 = (uint32_t*)(q1 + (size_t)row * DEMB);
    uint32_t* p0 = (uint32_t*)(q0 + (size_t)row * DEMB);
    p1[lane * 2]     = pack4i8(h[0], h[1], h[2], h[3]);
    p1[lane * 2 + 1] = pack4i8(h[4], h[5], h[6], h[7]);
    p0[lane * 2]     = pack4i8(l[0], l[1], l[2], l[3]);
    p0[lane * 2 + 1] = pack4i8(l[4], l[5], l[6], l[7]);
    if (lane == 0) s[row] = mx * (1.f / 16256.f);
}

// ---------------- quantized relation weights W_r^T: grid NREL*DHID, block din ----------------
__global__ void build_wrT_q(const float* __restrict__ bases,
                            const float* __restrict__ coeff,
                            int8_t* __restrict__ q1, int8_t* __restrict__ q0,
                            float* __restrict__ sc, int din) {
    __shared__ float red_[256];
    int bid = blockIdx.x;
    int r = bid >> 7;
    int n = bid & 127;
    int k = threadIdx.x;
    float v = 0.f;
    #pragma unroll
    for (int b = 0; b < NBAS; ++b)
        v += coeff[r * NBAS + b] * bases[((size_t)b * din + k) * DHID + n];
    red_[k] = fabsf(v);
    __syncthreads();
    for (int s = blockDim.x >> 1; s > 0; s >>= 1) {
        if (k < s) red_[k] = fmaxf(red_[k], red_[k + s]);
        __syncthreads();
    }
    float mx = fmaxf(red_[0], 1e-35f);
    float inv = 16256.f / mx;
    int h, l;
    quant1(v, inv, h, l);
    size_t o = (size_t)bid * din + k;
    q1[o] = (int8_t)h;
    q0[o] = (int8_t)l;
    if (k == 0) sc[bid] = mx * (1.f / 16256.f);
}

// ---------------- quantized selfw^T: grid DHID, block din ----------------
__global__ void build_selfT_q(const float* __restrict__ selfw,
                              int8_t* __restrict__ q1, int8_t* __restrict__ q0,
                              float* __restrict__ sc, int din) {
    __shared__ float red_[256];
    int n = blockIdx.x;
    int k = threadIdx.x;
    float v = selfw[(size_t)k * DHID + n];
    red_[k] = fabsf(v);
    __syncthreads();
    for (int s = blockDim.x >> 1; s > 0; s >>= 1) {
        if (k < s) red_[k] = fmaxf(red_[k], red_[k + s]);
        __syncthreads();
    }
    float mx = fmaxf(red_[0], 1e-35f);
    float inv = 16256.f / mx;
    int h, l;
    quant1(v, inv, h, l);
    size_t o = (size_t)n * din + k;
    q1[o] = (int8_t)h;
    q0[o] = (int8_t)l;
    if (k == 0) sc[n] = mx * (1.f / 16256.f);
}

// ---------------- quantized combined w1 head|tail transposed: grid 256, block 128 ----------------
__global__ void build_w1c_q(const float* __restrict__ w1,
                            int8_t* __restrict__ q1, int8_t* __restrict__ q0,
                            float* __restrict__ sc) {
    __shared__ float red_[128];
    int n = blockIdx.x;
    int k = threadIdx.x;
    float v = (n < DHID) ? w1[(size_t)k * DHID + n]
                         : w1[(size_t)(384 + k) * DHID + (n - DHID)];
    red_[k] = fabsf(v);
    __syncthreads();
    for (int s = 64; s > 0; s >>= 1) {
        if (k < s) red_[k] = fmaxf(red_[k], red_[k + s]);
        __syncthreads();
    }
    float mx = fmaxf(red_[0], 1e-35f);
    float inv = 16256.f / mx;
    int h, l;
    quant1(v, inv, h, l);
    size_t o = (size_t)n * DHID + k;
    q1[o] = (int8_t)h;
    q0[o] = (int8_t)l;
    if (k == 0) sc[n] = mx * (1.f / 16256.f);
}

// ---------------- relu + layernorm -> quantized int8 hi/lo ----------------
__global__ void relu_ln_q(const float* __restrict__ acc,
                          const float* __restrict__ gamma,
                          const float* __restrict__ beta,
                          int8_t* __restrict__ xq1, int8_t* __restrict__ xq0,
                          float* __restrict__ xs) {
    int n = blockIdx.x * 8 + (threadIdx.x >> 5);
    if (n >= N_NODES) return;
    int lane = threadIdx.x & 31;
    float4 v = ((const float4*)(acc + (size_t)n * DHID))[lane];
    v.x = fmaxf(v.x, 0.f); v.y = fmaxf(v.y, 0.f);
    v.z = fmaxf(v.z, 0.f); v.w = fmaxf(v.w, 0.f);
    float s = v.x + v.y + v.z + v.w;
    #pragma unroll
    for (int o = 16; o; o >>= 1) s += __shfl_xor_sync(0xFFFFFFFFu, s, o);
    float mu = s * (1.f / DHID);
    float dx = v.x - mu, dy = v.y - mu, dz = v.z - mu, dw = v.w - mu;
    float ss = dx * dx + dy * dy + dz * dz + dw * dw;
    #pragma unroll
    for (int o = 16; o; o >>= 1) ss += __shfl_xor_sync(0xFFFFFFFFu, ss, o);
    float invs = rsqrtf(ss * (1.f / DHID) + 1e-5f);
    float4 g = ((const float4*)gamma)[lane];
    float4 b = ((const float4*)beta)[lane];
    float ox = dx * invs * g.x + b.x;
    float oy = dy * invs * g.y + b.y;
    float oz = dz * invs * g.z + b.z;
    float ow = dw * invs * g.w + b.w;
    float mx = fmaxf(fmaxf(fabsf(ox), fabsf(oy)), fmaxf(fabsf(oz), fabsf(ow)));
    #pragma unroll
    for (int o = 16; o; o >>= 1) mx = fmaxf(mx, __shfl_xor_sync(0xFFFFFFFFu, mx, o));
    mx = fmaxf(mx, 1e-35f);
    float inv = 16256.f / mx;
    int h0, h1, h2, h3, l0, l1, l2, l3;
    quant1(ox, inv, h0, l0); quant1(oy, inv, h1, l1);
    quant1(oz, inv, h2, l2); quant1(ow, inv, h3, l3);
    ((uint32_t*)(xq1 + (size_t)n * DHID))[lane] = pack4i8(h0, h1, h2, h3);
    ((uint32_t*)(xq0 + (size_t)n * DHID))[lane] = pack4i8(l0, l1, l2, l3);
    if (lane == 0) xs[n] = mx * (1.f / 16256.f);
}

// ---------------- relproj ----------------
__global__ void relproj_k(const float* __restrict__ relemb,
                          const float* __restrict__ w1,
                          const float* __restrict__ b1,
                          float* __restrict__ rp) {
    int idx = blockIdx.x * blockDim.x + threadIdx.x;
    if (idx >= NREL * DHID) return;
    int r = idx >> 7;
    int j = idx & 127;
    float s = b1[j];
    for (int i = 0; i < DEMB; ++i)
        s = fmaf(relemb[r * DEMB + i], w1[(DHID + i) * DHID + j], s);
    rp[idx] = s;
}

// ---------------- score ----------------
__global__ void score_k(const int* __restrict__ head,
                        const int* __restrict__ rel,
                        const int* __restrict__ tail,
                        const float* __restrict__ HPTP,
                        const float* __restrict__ rp,
                        const float* __restrict__ w2,
                        const float* __restrict__ b2,
                        float* __restrict__ out) {
    int q = blockIdx.x * 8 + (threadIdx.x >> 5);
    if (q >= NQUERY) return;
    int lane = threadIdx.x & 31;
    int h = head[q], r = rel[q], t = tail[q];
    float4 a = ((const float4*)(HPTP + (size_t)h * 256))[lane];
    float4 bb = ((const float4*)(HPTP + (size_t)t * 256 + DHID))[lane];
    float4 c = ((const float4*)(rp + (size_t)r * DHID))[lane];
    float4 w = ((const float4*)w2)[lane];
    float s = fmaxf(a.x + bb.x + c.x, 0.f) * w.x
            + fmaxf(a.y + bb.y + c.y, 0.f) * w.y
            + fmaxf(a.z + bb.z + c.z, 0.f) * w.z
            + fmaxf(a.w + bb.w + c.w, 0.f) * w.w;
    #pragma unroll
    for (int o = 16; o; o >>= 1) s += __shfl_xor_sync(0xFFFFFFFFu, s, o);
    if (lane == 0) out[q] = s + b2[0];
}

// ---------------- launch ----------------
extern "C" void kernel_launch(void* const* d_in, const int* in_sizes, int n_in,
                              void* d_out, int out_size) {
    (void)in_sizes; (void)n_in; (void)out_size;
    const int*   edge_index   = (const int*)d_in[0];
    const int*   edge_type    = (const int*)d_in[1];
    const int*   head_ids     = (const int*)d_in[2];
    const int*   relation_ids = (const int*)d_in[3];
    const int*   tail_ids     = (const int*)d_in[4];
    const float* entity_emb   = (const float*)d_in[5];
    const float* relation_emb = (const float*)d_in[6];
    const float* bases0       = (const float*)d_in[7];
    const float* coeff0       = (const float*)d_in[8];
    const float* selfw0       = (const float*)d_in[9];
    const float* bases1       = (const float*)d_in[10];
    const float* coeff1       = (const float*)d_in[11];
    const float* selfw1       = (const float*)d_in[12];
    const float* ln0_g        = (const float*)d_in[13];
    const float* ln0_b        = (const float*)d_in[14];
    const float* ln1_g        = (const float*)d_in[15];
    const float* ln1_b        = (const float*)d_in[16];
    const float* w1           = (const float*)d_in[17];
    const float* b1           = (const float*)d_in[18];
    const float* w2           = (const float*)d_in[19];
    const float* b2           = (const float*)d_in[20];
    float* out = (float*)d_out;

    int8_t *Eq1, *Eq0, *Wq1, *Wq0, *Sq1, *Sq0, *xq1, *xq0, *w1q1, *w1q0;
    float *Es, *Wsc, *Ssc, *xs, *w1sc, *acc, *HPTP, *rp;
    cudaGetSymbolAddress((void**)&Eq1, g_Eq1);
    cudaGetSymbolAddress((void**)&Eq0, g_Eq0);
    cudaGetSymbolAddress((void**)&Es,  g_Es);
    cudaGetSymbolAddress((void**)&Wq1, g_Wq1);
    cudaGetSymbolAddress((void**)&Wq0, g_Wq0);
    cudaGetSymbolAddress((void**)&Wsc, g_Wsc);
    cudaGetSymbolAddress((void**)&Sq1, g_Sq1);
    cudaGetSymbolAddress((void**)&Sq0, g_Sq0);
    cudaGetSymbolAddress((void**)&Ssc, g_Ssc);
    cudaGetSymbolAddress((void**)&xq1, g_xq1);
    cudaGetSymbolAddress((void**)&xq0, g_xq0);
    cudaGetSymbolAddress((void**)&xs,  g_xs);
    cudaGetSymbolAddress((void**)&w1q1, g_w1q1);
    cudaGetSymbolAddress((void**)&w1q0, g_w1q0);
    cudaGetSymbolAddress((void**)&w1sc, g_w1sc);
    cudaGetSymbolAddress((void**)&acc,  g_acc);
    cudaGetSymbolAddress((void**)&HPTP, g_HPTP);
    cudaGetSymbolAddress((void**)&rp,   g_rp);

    cudaFuncSetAttribute(gemm_s8,  cudaFuncAttributeMaxDynamicSharedMemorySize, SMEM8);
    cudaFuncSetAttribute(egemm_s8, cudaFuncAttributeMaxDynamicSharedMemorySize, SMEM8);

    const int* erow = edge_index;
    const int* ecol = edge_index + NEDGE;
    const int nM = (N_NODES + 127) / 128;   // 391

    // ----- edge sort by relation -----
    zero16<<<1, 32>>>();
    hist_k<<<(NEDGE + 255) / 256, 256>>>(edge_type);
    prefix_k<<<1, 1>>>();
    scatter_k<<<(NEDGE + 255) / 256, 256>>>(erow, ecol, edge_type);

    // ----- layer 0 -----
    quantE<<<(N_NODES + 7) / 8, 256>>>(entity_emb, Eq1, Eq0, Es);
    build_wrT_q<<<NREL * DHID, DEMB>>>(bases0, coeff0, Wq1, Wq0, Wsc, DEMB);
    build_selfT_q<<<DHID, DEMB>>>(selfw0, Sq1, Sq0, Ssc, DEMB);
    gemm_s8<<<dim3(1, nM), 512, SMEM8>>>(N_NODES, DEMB, Eq1, Eq0, Es, Sq1, Sq0, Ssc, acc, DHID);
    egemm_s8<<<EGRID, 512, SMEM8>>>(DEMB, Eq1, Eq0, Es, Wq1, Wq0, Wsc, acc);
    relu_ln_q<<<(N_NODES + 7) / 8, 256>>>(acc, ln0_g, ln0_b, xq1, xq0, xs);

    // ----- layer 1 -----
    build_wrT_q<<<NREL * DHID, DHID>>>(bases1, coeff1, Wq1, Wq0, Wsc, DHID);
    build_selfT_q<<<DHID, DHID>>>(selfw1, Sq1, Sq0, Ssc, DHID);
    gemm_s8<<<dim3(1, nM), 512, SMEM8>>>(N_NODES, DHID, xq1, xq0, xs, Sq1, Sq0, Ssc, acc, DHID);
    egemm_s8<<<EGRID, 512, SMEM8>>>(DHID, xq1, xq0, xs, Wq1, Wq0, Wsc, acc);
    relu_ln_q<<<(N_NODES + 7) / 8, 256>>>(acc, ln1_g, ln1_b, xq1, xq0, xs);

    // ----- scoring -----
    relproj_k<<<(NREL * DHID + 255) / 256, 256>>>(relation_emb, w1, b1, rp);
    build_w1c_q<<<2 * DHID, DHID>>>(w1, w1q1, w1q0, w1sc);
    gemm_s8<<<dim3(2, nM), 512, SMEM8>>>(N_NODES, DHID, xq1, xq0, xs, w1q1, w1q0, w1sc, HPTP, 256);
    score_k<<<(NQUERY + 7) / 8, 256>>>(head_ids, relation_ids, tail_ids, HPTP, rp, w2, b2, out);
}